// round 6
// baseline (speedup 1.0000x reference)
#include <cuda_runtime.h>
#include <cuda_bf16.h>

#define N_IN    11008
#define N_OUT   4096
#define TOPK_K  5504
#define N_CACHE 64
#define NBW     ((N_IN + 31) / 32)   // 344 bitset words
#define NBLK    64                   // pre-work blocks
#define SLICE   (N_IN / NBLK)        // 172 elements per block

// ---- device-global scratch (allocation-free; fully rewritten each call) ----
__device__ __align__(16) float g_xm[N_IN];
__device__ unsigned g_cbits[N_CACHE][NBW];
__device__ unsigned g_hist0[2048];
__device__ unsigned g_hist1[2048];
__device__ unsigned g_hist2[1024];
__device__ int g_tiec[NBLK];
__device__ int g_inter[N_CACHE];
__device__ unsigned g_barcnt;        // monotonic grid-barrier counter (replay-safe)

// Replay-safe grid barrier among the NBLK blocks.
__device__ __forceinline__ void grid_barrier() {
    __syncthreads();
    if (threadIdx.x == 0) {
        __threadfence();
        unsigned old = atomicAdd(&g_barcnt, 1u);
        unsigned target = (old / NBLK + 1u) * NBLK;
        unsigned cur;
        do {
            asm volatile("ld.acquire.gpu.u32 %0, [%1];"
                         : "=r"(cur) : "l"(&g_barcnt) : "memory");
        } while (cur < target);
    }
    __syncthreads();
}

// Block-wide inclusive scan over 1024 threads (one int each).
__device__ __forceinline__ int block_incl_scan(int v, int lane, int wid, int* sbuf) {
    __syncthreads();
    #pragma unroll
    for (int o = 1; o < 32; o <<= 1) {
        int t = __shfl_up_sync(0xffffffffu, v, o);
        if (lane >= o) v += t;
    }
    if (lane == 31) sbuf[wid] = v;
    __syncthreads();
    if (wid == 0) {
        int w = sbuf[lane];
        #pragma unroll
        for (int o = 1; o < 32; o <<= 1) {
            int t = __shfl_up_sync(0xffffffffu, w, o);
            if (lane >= o) w += t;
        }
        sbuf[lane] = w;
    }
    __syncthreads();
    if (wid > 0) v += sbuf[wid - 1];
    return v;
}

// ============================================================================
// Fused pre-work, 64 blocks x 1024 threads:
//   distributed 3-level radix top-K + per-slice intersection + decision + xm.
// ============================================================================
__global__ void __launch_bounds__(1024) fused_kernel(const float* __restrict__ x,
                                                     const int* __restrict__ cached) {
    __shared__ unsigned cbits[NBW];
    __shared__ int scanbuf[32];
    __shared__ int s_b, s_G, s_need, s_use, s_best, s_base;
    __shared__ unsigned s_T;
    __shared__ unsigned sbits[7];
    __shared__ int ssum[N_CACHE];

    const int tid  = threadIdx.x;
    const int lane = tid & 31, wid = tid >> 5;
    const int b = blockIdx.x;
    const int base = b * SLICE;

    // ---- Phase Z: zero global hists (distributed) + my g_inter slot ----
    if (tid < 32) g_hist0[b * 32 + tid] = 0;
    else if (tid < 64) g_hist1[b * 32 + (tid - 32)] = 0;
    else if (tid < 80) g_hist2[b * 16 + (tid - 64)] = 0;
    else if (tid == 80) g_inter[b] = 0;

    // ---- Phase 0: dedup bitset for cache b; publish to global ----
    for (int i = tid; i < NBW; i += 1024) cbits[i] = 0;
    __syncthreads();
    {
        const int* row = cached + b * TOPK_K;
        for (int k = tid; k < TOPK_K; k += 1024) {
            int idx = row[k];
            atomicOr(&cbits[idx >> 5], 1u << (idx & 31));
        }
    }
    __syncthreads();
    for (int i = tid; i < NBW; i += 1024) g_cbits[b][i] = cbits[i];

    grid_barrier();   // B0: hists zeroed, cbits published

    // My slice element (one per thread; SLICE=172 < 1024).
    unsigned u = 0;
    float xv = 0.0f;
    if (tid < SLICE) {
        xv = x[base + tid];
        u = __float_as_uint(xv) & 0x7FFFFFFFu;
    }

    // ---- level 0 fill: bits [30:21] ----
    if (tid < SLICE) atomicAdd(&g_hist0[u >> 21], 1u);
    grid_barrier();   // B1

    {
        const int j0 = 2047 - 2 * tid, j1 = j0 - 1;
        const int h0 = g_hist0[j0], h1 = g_hist0[j1];
        int S = block_incl_scan(h0 + h1, lane, wid, scanbuf);
        int excl = S - h0 - h1;
        const int Kr = TOPK_K;
        if (excl + h0 >= Kr && excl < Kr)   { s_b = j0; s_G = excl; }
        else if (S >= Kr && excl + h0 < Kr) { s_b = j1; s_G = excl + h0; }
    }
    __syncthreads();
    const int b0 = s_b, G0 = s_G;

    // ---- level 1 fill: bits [20:10] ----
    if (tid < SLICE && (int)(u >> 21) == b0)
        atomicAdd(&g_hist1[(u >> 10) & 0x7FF], 1u);
    grid_barrier();   // B2

    {
        const int j0 = 2047 - 2 * tid, j1 = j0 - 1;
        const int h0 = g_hist1[j0], h1 = g_hist1[j1];
        int S = block_incl_scan(h0 + h1, lane, wid, scanbuf);
        int excl = S - h0 - h1;
        const int Kr = TOPK_K - G0;
        if (excl + h0 >= Kr && excl < Kr)   { s_b = j0; s_G = G0 + excl; }
        else if (S >= Kr && excl + h0 < Kr) { s_b = j1; s_G = G0 + excl + h0; }
    }
    __syncthreads();
    const int b1 = s_b, G1 = s_G;

    // ---- level 2 fill: bits [9:0] ----
    const unsigned top22 = ((unsigned)b0 << 21) | ((unsigned)b1 << 10);
    if (tid < SLICE && (u & 0xFFFFFC00u) == top22)
        atomicAdd(&g_hist2[u & 0x3FF], 1u);
    grid_barrier();   // B3

    {
        const int j = 1023 - tid;
        const int h = g_hist2[j];
        int S = block_incl_scan(h, lane, wid, scanbuf);
        int excl = S - h;
        const int Kr = TOPK_K - G1;
        if (S >= Kr && excl < Kr) { s_T = top22 | (unsigned)j; s_need = Kr - excl; }
    }
    __syncthreads();
    const unsigned T = s_T;
    const int need = s_need;

    // ---- tie counting: global rank by index = block order then tid order ----
    int tie = (tid < SLICE && u == T) ? 1 : 0;
    int incl = block_incl_scan(tie, lane, wid, scanbuf);
    const int rank_in_blk = incl - tie;
    if (tid == 1023) g_tiec[b] = incl;
    grid_barrier();   // B4: tie totals + (implicitly) all blocks past fills

    if (tid == 0) {
        int s = 0;
        for (int i = 0; i < b; i++) s += g_tiec[i];
        s_base = s;
    }
    // zero slice-window bitset + partial sums
    if (tid < 7) sbits[tid] = 0;
    if (tid >= 32 && tid < 32 + N_CACHE) ssum[tid - 32] = 0;
    __syncthreads();

    int sel = 0;
    if (tid < SLICE) {
        if (u > T) sel = 1;
        else if (tie) sel = (s_base + rank_in_blk < need);
        if (sel) atomicOr(&sbits[((base + tid) >> 5) - (base >> 5)],
                          1u << ((base + tid) & 31));
    }
    __syncthreads();

    // ---- per-slice intersection vs all 64 cache bitsets ----
    {
        const int w_start = base >> 5;
        const int nwords  = ((base + SLICE - 1) >> 5) - w_start + 1;  // 6 or 7
        if (tid < 512) {
            const int c = tid >> 3, j = tid & 7;
            if (j < nwords) {
                int v = __popc(sbits[j] & g_cbits[c][w_start + j]);
                if (v) atomicAdd(&ssum[c], v);
            }
        }
        __syncthreads();
        if (tid < N_CACHE && ssum[tid]) atomicAdd(&g_inter[tid], ssum[tid]);
    }

    grid_barrier();   // B5: g_inter complete

    // ---- decision (redundant per block) + xm slice build ----
    if (tid == 0) {
        float best = -1.0f; int bi = 0;
        #pragma unroll
        for (int i = 0; i < N_CACHE; i++) {
            float r = (float)g_inter[i] / (float)TOPK_K;
            if (r > best) { best = r; bi = i; }   // first-max = argmax
        }
        s_use  = (best >= 0.9f) ? 1 : 0;
        s_best = bi;
    }
    __syncthreads();

    if (!s_use) {
        if (tid < SLICE) g_xm[base + tid] = sel ? xv : 0.0f;
    } else {
        if (tid < SLICE) g_xm[base + tid] = 0.0f;
        grid_barrier();                          // B6 (all blocks take this path)
        const int kbase = b * (TOPK_K / NBLK);   // 86 per block
        const int* brow = cached + s_best * TOPK_K;
        for (int k = kbase + tid; k < kbase + TOPK_K / NBLK; k += 1024) {
            int idx = brow[k];
            atomicAdd(&g_xm[idx], x[idx]);       // duplicates = multiplicity
        }
    }
}

// ============================================================================
// GEMV: out = W @ xm + bias.  2-way K-split per row: 8192 warps total for
// deeper chip-wide DRAM queues. Block = 8 warps = 4 rows; smem combine.
// ============================================================================
__global__ void __launch_bounds__(256) gemv_kernel(const float* __restrict__ W,
                                                   const float* __restrict__ bias,
                                                   float* __restrict__ out) {
    __shared__ float s8[8];
    const int wid  = threadIdx.x >> 5;          // 0..7
    const int lane = threadIdx.x & 31;
    const int row  = blockIdx.x * 4 + (wid >> 1);
    const int half = wid & 1;                   // which half of the row

    const float4* __restrict__ w4 =
        (const float4*)(W + (long long)row * N_IN) + half * (N_IN / 8);
    const float4* __restrict__ x4 =
        (const float4*)g_xm + half * (N_IN / 8);

    float a0 = 0.0f, a1 = 0.0f;
    // half-row = 1376 float4 = 43 iterations of 32 lanes.
    #pragma unroll 4
    for (int it = 0; it < 43; it++) {
        const int j = lane + it * 32;
        float4 w = __ldcs(w4 + j);
        float4 v = x4[j];
        a0 += w.x * v.x + w.y * v.y;
        a1 += w.z * v.z + w.w * v.w;
    }
    float acc = a0 + a1;
    #pragma unroll
    for (int o = 16; o; o >>= 1) acc += __shfl_down_sync(0xffffffffu, acc, o);
    if (lane == 0) s8[wid] = acc;
    __syncthreads();
    if (threadIdx.x < 4) {
        const int r = blockIdx.x * 4 + threadIdx.x;
        out[r] = s8[2 * threadIdx.x] + s8[2 * threadIdx.x + 1] + bias[r];
    }
}

// ============================================================================
extern "C" void kernel_launch(void* const* d_in, const int* in_sizes, int n_in,
                              void* d_out, int out_size) {
    const float* x      = (const float*)d_in[0];
    const float* W      = (const float*)d_in[1];
    const float* bias   = (const float*)d_in[2];
    const int*   cached = (const int*)d_in[3];
    float*       out    = (float*)d_out;

    fused_kernel<<<NBLK, 1024>>>(x, cached);
    gemv_kernel<<<N_OUT / 4, 256>>>(W, bias, out);
}

// round 7
// speedup vs baseline: 1.0065x; 1.0065x over previous
#include <cuda_runtime.h>
#include <cuda_bf16.h>

#define N_IN   11008
#define N_OUT  4096
#define TOPK_K 5504
#define N_CACHE 64
#define NBW ((N_IN + 31) / 32)   // 344 bitset words
#define NBLK 64                  // fused kernel grid size

// ---- device-global scratch (allocation-free) ----
__device__ __align__(16) float g_xm[N_IN];
__device__ unsigned g_maskbits[NBW];
__device__ int g_inter[N_CACHE];
__device__ unsigned g_barcnt;    // monotonic grid-barrier counter (replay-safe)

// Replay-safe grid barrier: monotonic counter, generation = count / NBLK.
__device__ __forceinline__ void grid_barrier() {
    __syncthreads();
    if (threadIdx.x == 0) {
        __threadfence();
        unsigned old = atomicAdd(&g_barcnt, 1u);
        unsigned target = (old / NBLK + 1u) * NBLK;
        unsigned cur;
        do {
            asm volatile("ld.acquire.gpu.u32 %0, [%1];"
                         : "=r"(cur) : "l"(&g_barcnt) : "memory");
        } while (cur < target);
    }
    __syncthreads();
}

// Block-wide inclusive scan over 1024 threads (one int each).
__device__ __forceinline__ int block_incl_scan(int v, int lane, int wid, int* sbuf) {
    __syncthreads();
    #pragma unroll
    for (int o = 1; o < 32; o <<= 1) {
        int t = __shfl_up_sync(0xffffffffu, v, o);
        if (lane >= o) v += t;
    }
    if (lane == 31) sbuf[wid] = v;
    __syncthreads();
    if (wid == 0) {
        int w = sbuf[lane];
        #pragma unroll
        for (int o = 1; o < 32; o <<= 1) {
            int t = __shfl_up_sync(0xffffffffu, w, o);
            if (lane >= o) w += t;
        }
        sbuf[lane] = w;
    }
    __syncthreads();
    if (wid > 0) v += sbuf[wid - 1];
    return v;
}

// Top-K select on |x|, 3-level radix histogram, executed by block 0 only.
__device__ void do_select(const float* __restrict__ x,
                          unsigned* hist, unsigned* bits, int* scanbuf,
                          int* s_b, int* s_G, unsigned* s_T, int* s_need) {
    const int tid  = threadIdx.x;
    const int lane = tid & 31, wid = tid >> 5;

    for (int i = tid; i < NBW; i += 1024) bits[i] = 0;

    // ---- level 0: bits [30:21] ----
    for (int i = tid; i < 2048; i += 1024) hist[i] = 0;
    __syncthreads();
    for (int i = tid; i < N_IN; i += 1024) {
        unsigned u = __float_as_uint(x[i]) & 0x7FFFFFFFu;
        atomicAdd(&hist[u >> 21], 1u);
    }
    __syncthreads();
    {
        const int j0 = 2047 - 2 * tid, j1 = j0 - 1;
        const int h0 = hist[j0], h1 = hist[j1];
        int S = block_incl_scan(h0 + h1, lane, wid, scanbuf);
        int excl = S - h0 - h1;
        const int Kr = TOPK_K;
        if (excl + h0 >= Kr && excl < Kr)   { *s_b = j0; *s_G = excl; }
        else if (S >= Kr && excl + h0 < Kr) { *s_b = j1; *s_G = excl + h0; }
    }
    __syncthreads();
    const int b0 = *s_b, G0 = *s_G;

    // ---- level 1: bits [20:10] ----
    __syncthreads();
    for (int i = tid; i < 2048; i += 1024) hist[i] = 0;
    __syncthreads();
    for (int i = tid; i < N_IN; i += 1024) {
        unsigned u = __float_as_uint(x[i]) & 0x7FFFFFFFu;
        if ((int)(u >> 21) == b0) atomicAdd(&hist[(u >> 10) & 0x7FF], 1u);
    }
    __syncthreads();
    {
        const int j0 = 2047 - 2 * tid, j1 = j0 - 1;
        const int h0 = hist[j0], h1 = hist[j1];
        int S = block_incl_scan(h0 + h1, lane, wid, scanbuf);
        int excl = S - h0 - h1;
        const int Kr = TOPK_K - G0;
        if (excl + h0 >= Kr && excl < Kr)   { *s_b = j0; *s_G = G0 + excl; }
        else if (S >= Kr && excl + h0 < Kr) { *s_b = j1; *s_G = G0 + excl + h0; }
    }
    __syncthreads();
    const int b1 = *s_b, G1 = *s_G;

    // ---- level 2: bits [9:0] ----
    __syncthreads();
    for (int i = tid; i < 2048; i += 1024) hist[i] = 0;
    __syncthreads();
    const unsigned top22 = ((unsigned)b0 << 21) | ((unsigned)b1 << 10);
    for (int i = tid; i < N_IN; i += 1024) {
        unsigned u = __float_as_uint(x[i]) & 0x7FFFFFFFu;
        if ((u & 0xFFFFFC00u) == top22) atomicAdd(&hist[u & 0x3FF], 1u);
    }
    __syncthreads();
    {
        const int j = 1023 - tid;
        const int h = hist[j];
        int S = block_incl_scan(h, lane, wid, scanbuf);
        int excl = S - h;
        const int Kr = TOPK_K - G1;
        if (S >= Kr && excl < Kr) { *s_T = top22 | (unsigned)j; *s_need = Kr - excl; }
    }
    __syncthreads();
    const unsigned T = *s_T;
    const int need = *s_need;

    // ---- mask build with smallest-index tie-break ----
    const int CHUNK = (N_IN + 1023) / 1024;   // 11
    const int start = tid * CHUNK;
    const int end   = min(start + CHUNK, N_IN);

    int tieCnt = 0;
    for (int i = start; i < end; i++) {
        unsigned u = __float_as_uint(x[i]) & 0x7FFFFFFFu;
        if (u == T) tieCnt++;
    }
    int incl = block_incl_scan(tieCnt, lane, wid, scanbuf);
    int tieRank = incl - tieCnt;

    for (int i = start; i < end; i++) {
        unsigned u = __float_as_uint(x[i]) & 0x7FFFFFFFu;
        int sel;
        if (u > T)       sel = 1;
        else if (u == T) { sel = (tieRank < need); tieRank++; }
        else             sel = 0;
        if (sel) atomicOr(&bits[i >> 5], 1u << (i & 31));
    }
    __syncthreads();
    for (int i = tid; i < NBW; i += 1024) g_maskbits[i] = bits[i];
}

// ============================================================================
// Fused kernel: recall bitsets + top-K select (block 0) | popc | decide + xm.
// ============================================================================
__global__ void __launch_bounds__(1024) fused_kernel(const float* __restrict__ x,
                                                     const int* __restrict__ cached) {
    __shared__ unsigned cbits[NBW];
    __shared__ unsigned hist[2048];
    __shared__ unsigned bits[NBW];
    __shared__ int scanbuf[32];
    __shared__ int wsum[32];
    __shared__ int s_b, s_G, s_need, s_use, s_best;
    __shared__ unsigned s_T;

    const int b = blockIdx.x, tid = threadIdx.x;
    const int lane = tid & 31, wid = tid >> 5;

    // ---- Phase 0: dedup bitset for cache b ----
    for (int i = tid; i < NBW; i += 1024) cbits[i] = 0;
    __syncthreads();
    {
        const int* row = cached + b * TOPK_K;
        for (int k = tid; k < TOPK_K; k += 1024) {
            int idx = row[k];
            atomicOr(&cbits[idx >> 5], 1u << (idx & 31));
        }
    }

    // ---- Phase 0b: block 0 runs top-K select ----
    if (b == 0)
        do_select(x, hist, bits, scanbuf, &s_b, &s_G, &s_T, &s_need);

    grid_barrier();   // g_maskbits published

    // ---- Phase 1: deduped intersection count ----
    int cnt = 0;
    for (int i = tid; i < NBW; i += 1024) cnt += __popc(cbits[i] & g_maskbits[i]);
    #pragma unroll
    for (int o = 16; o; o >>= 1) cnt += __shfl_down_sync(0xffffffffu, cnt, o);
    if (lane == 0) wsum[wid] = cnt;
    __syncthreads();
    if (tid == 0) {
        int s = 0;
        #pragma unroll
        for (int i = 0; i < 32; i++) s += wsum[i];
        g_inter[b] = s;
    }

    grid_barrier();   // g_inter published

    // ---- Phase 2: decision (redundant per block) + xm slice build ----
    if (tid == 0) {
        float best = -1.0f; int bi = 0;
        #pragma unroll
        for (int i = 0; i < N_CACHE; i++) {
            float r = (float)g_inter[i] / (float)TOPK_K;
            if (r > best) { best = r; bi = i; }   // first-max = argmax
        }
        s_use  = (best >= 0.9f) ? 1 : 0;
        s_best = bi;
    }
    __syncthreads();

    const int base = b * (N_IN / NBLK);     // 172 per block
    if (!s_use) {
        for (int i = base + tid; i < base + N_IN / NBLK; i += 1024) {
            int sel = (g_maskbits[i >> 5] >> (i & 31)) & 1;
            g_xm[i] = sel ? x[i] : 0.0f;
        }
    } else {
        for (int i = base + tid; i < base + N_IN / NBLK; i += 1024)
            g_xm[i] = 0.0f;
        grid_barrier();                      // all of xm zeroed
        const int kbase = b * (TOPK_K / NBLK);   // 86 per block
        const int* brow = cached + s_best * TOPK_K;
        for (int k = kbase + tid; k < kbase + TOPK_K / NBLK; k += 1024) {
            int idx = brow[k];
            atomicAdd(&g_xm[idx], x[idx]);   // duplicates = multiplicity
        }
    }
}

// ============================================================================
// GEMV: out = W @ xm + bias. TWO rows per warp (rows gw and gw+2048):
// same 4096 DRAM stream count as the 34.7us version, but xm loaded once per
// row pair and doubled per-warp W MLP. 512 blocks x 128 threads.
// ============================================================================
__global__ void __launch_bounds__(128) gemv_kernel(const float* __restrict__ W,
                                                   const float* __restrict__ bias,
                                                   float* __restrict__ out) {
    const int gw   = (blockIdx.x * 128 + threadIdx.x) >> 5;   // 0..2047
    const int lane = threadIdx.x & 31;
    const int rowA = gw;
    const int rowB = gw + 2048;

    const float4* __restrict__ wa = (const float4*)(W + (long long)rowA * N_IN);
    const float4* __restrict__ wb = (const float4*)(W + (long long)rowB * N_IN);
    const float4* __restrict__ x4 = (const float4*)g_xm;

    float a0 = 0.0f, a1 = 0.0f, b0 = 0.0f, b1 = 0.0f;
    // N_IN/4 = 2752 = 43 * 64: two float4 per lane per iteration per row.
    #pragma unroll 4
    for (int it = 0; it < 43; it++) {
        const int j = lane + it * 64;
        float4 v  = x4[j];
        float4 v2 = x4[j + 32];
        float4 wA  = __ldcs(wa + j);
        float4 wA2 = __ldcs(wa + j + 32);
        float4 wB  = __ldcs(wb + j);
        float4 wB2 = __ldcs(wb + j + 32);
        a0 += wA.x * v.x  + wA.y * v.y;
        a1 += wA.z * v.z  + wA.w * v.w;
        a0 += wA2.x * v2.x + wA2.y * v2.y;
        a1 += wA2.z * v2.z + wA2.w * v2.w;
        b0 += wB.x * v.x  + wB.y * v.y;
        b1 += wB.z * v.z  + wB.w * v.w;
        b0 += wB2.x * v2.x + wB2.y * v2.y;
        b1 += wB2.z * v2.z + wB2.w * v2.w;
    }
    float accA = a0 + a1;
    float accB = b0 + b1;
    #pragma unroll
    for (int o = 16; o; o >>= 1) {
        accA += __shfl_down_sync(0xffffffffu, accA, o);
        accB += __shfl_down_sync(0xffffffffu, accB, o);
    }
    if (lane == 0) {
        out[rowA] = accA + bias[rowA];
        out[rowB] = accB + bias[rowB];
    }
}

// ============================================================================
extern "C" void kernel_launch(void* const* d_in, const int* in_sizes, int n_in,
                              void* d_out, int out_size) {
    const float* x      = (const float*)d_in[0];
    const float* W      = (const float*)d_in[1];
    const float* bias   = (const float*)d_in[2];
    const int*   cached = (const int*)d_in[3];
    float*       out    = (float*)d_out;

    fused_kernel<<<NBLK, 1024>>>(x, cached);
    gemv_kernel<<<512, 128>>>(W, bias, out);
}

// round 8
// speedup vs baseline: 1.1056x; 1.0985x over previous
#include <cuda_runtime.h>
#include <cuda_bf16.h>

#define N_IN    11008
#define N_OUT   4096
#define TOPK_K  5504
#define N_CACHE 64
#define NBW     344            // ceil(11008/32)
#define TPB     256
#define GRID    512            // all co-resident (4 blocks/SM needed, 8 possible)
#define SELB    64             // select/recall blocks
#define SLICE   172            // N_IN / SELB

// ---- device-global scratch (allocation-free; fully rewritten each call) ----
__device__ __align__(16) float g_xm[N_IN];
__device__ unsigned g_maskbits[NBW];
__device__ unsigned g_h[4][256];
__device__ int g_tiec[SELB];
__device__ int g_inter[N_CACHE];
__device__ unsigned g_barcnt;   // monotonic grid-barrier counter (replay-safe)

// Replay-safe grid barrier across all GRID blocks.
__device__ __forceinline__ void grid_barrier() {
    __syncthreads();
    if (threadIdx.x == 0) {
        __threadfence();
        unsigned old = atomicAdd(&g_barcnt, 1u);
        unsigned target = (old / GRID + 1u) * GRID;
        unsigned cur;
        do {
            asm volatile("ld.acquire.gpu.u32 %0, [%1];"
                         : "=r"(cur) : "l"(&g_barcnt) : "memory");
        } while (cur < target);
    }
    __syncthreads();
}

// 256-thread block inclusive scan (one int per thread).
__device__ __forceinline__ int scan256(int v, int lane, int wid, int* sbuf) {
    __syncthreads();                 // protect sbuf from prior use
    #pragma unroll
    for (int o = 1; o < 32; o <<= 1) {
        int t = __shfl_up_sync(0xffffffffu, v, o);
        if (lane >= o) v += t;
    }
    if (lane == 31) sbuf[wid] = v;
    __syncthreads();
    if (wid == 0) {
        int w = (lane < 8) ? sbuf[lane] : 0;
        #pragma unroll
        for (int o = 1; o < 8; o <<= 1) {
            int t = __shfl_up_sync(0xffffffffu, w, o);
            if (lane >= o) w += t;
        }
        if (lane < 8) sbuf[lane] = w;
    }
    __syncthreads();
    if (wid > 0) v += sbuf[wid - 1];
    return v;
}

// ============================================================================
// Mega-kernel: select + recall + decide + xm + GEMV in ONE launch.
// ============================================================================
__global__ void __launch_bounds__(TPB, 4)
mega_kernel(const float* __restrict__ x, const int* __restrict__ cached,
            const float* __restrict__ W, const float* __restrict__ bias,
            float* __restrict__ out) {
    __shared__ unsigned cbits[NBW];
    __shared__ int sbuf[8];
    __shared__ int s_d, s_excl, s_base, s_use, s_best;

    const int b = blockIdx.x, tid = threadIdx.x;
    const int lane = tid & 31, wid = tid >> 5;
    const int base = b * SLICE;

    // ---- Phase A: zero scratch; build cache bitsets; load slice element ----
    if (b == 64)
        for (int i = tid; i < 4 * 256; i += TPB) ((unsigned*)g_h)[i] = 0;
    if (b == 65)
        for (int i = tid; i < NBW; i += TPB) g_maskbits[i] = 0;

    unsigned u = 0;
    float xv = 0.0f;
    if (b < SELB) {
        for (int i = tid; i < NBW; i += TPB) cbits[i] = 0;
        __syncthreads();
        const int* row = cached + b * TOPK_K;
        for (int k = tid; k < TOPK_K; k += TPB) {
            int idx = row[k];
            atomicOr(&cbits[idx >> 5], 1u << (idx & 31));
        }
        if (tid < SLICE) {
            xv = x[base + tid];
            u = __float_as_uint(xv) & 0x7FFFFFFFu;
        }
    }
    grid_barrier();   // B0: scratch zeroed

    // ---- distributed radix-256 select, 4 levels ----
    int Kr = TOPK_K;                               // remaining within tie class
    bool matched = (b < SELB) && (tid < SLICE);    // element still in tie class
    bool gt = false;                               // element strictly > threshold
    #pragma unroll
    for (int l = 0; l < 4; l++) {
        const int shift = 24 - 8 * l;
        if (b < SELB && matched)
            atomicAdd(&g_h[l][(u >> shift) & 255], 1u);
        grid_barrier();                            // B1..B4: level hist complete
        if (b < SELB) {
            const int j = 255 - tid;
            const int h = (int)g_h[l][j];
            int S = scan256(h, lane, wid, sbuf);   // count(digit >= j) in class
            int excl = S - h;                      // count(digit >  j)
            if (S >= Kr && excl < Kr) { s_d = j; s_excl = excl; }
            __syncthreads();
            const int d = s_d;
            Kr -= s_excl;
            const int dig = (u >> shift) & 255;
            if (matched && dig > d) gt = true;
            matched = matched && (dig == d);
        }
    }
    // Kr == number of threshold-equal elements to take ("need").

    // ---- global tie rank (index order: block asc, tid asc) + mask build ----
    if (b < SELB) {
        int tie = matched ? 1 : 0;
        int incl = scan256(tie, lane, wid, sbuf);
        const int rank = incl - tie;
        if (tid == TPB - 1) g_tiec[b] = incl;      // block total
        grid_barrier();                            // B5
        if (tid == 0) {
            int s = 0;
            for (int i = 0; i < b; i++) s += g_tiec[i];
            s_base = s;
        }
        __syncthreads();
        if (tid < SLICE) {
            bool sel = gt || (matched && (s_base + rank < Kr));
            if (sel) atomicOr(&g_maskbits[(base + tid) >> 5],
                              1u << ((base + tid) & 31));
        }
    } else {
        grid_barrier();                            // B5
    }
    grid_barrier();                                // B6: maskbits final

    // ---- deduped intersection ----
    if (b < SELB) {
        int cnt = 0;
        for (int i = tid; i < NBW; i += TPB)
            cnt += __popc(cbits[i] & g_maskbits[i]);
        #pragma unroll
        for (int o = 16; o; o >>= 1) cnt += __shfl_down_sync(0xffffffffu, cnt, o);
        __syncthreads();                           // protect sbuf
        if (lane == 0) sbuf[wid] = cnt;
        __syncthreads();
        if (tid == 0) {
            int s = 0;
            #pragma unroll
            for (int i = 0; i < 8; i++) s += sbuf[i];
            g_inter[b] = s;
        }
    }
    grid_barrier();                                // B7: g_inter published

    // ---- decision (redundant per block) + xm build ----
    if (tid == 0) {
        float best = -1.0f; int bi = 0;
        #pragma unroll
        for (int i = 0; i < N_CACHE; i++) {
            float r = (float)g_inter[i] / (float)TOPK_K;
            if (r > best) { best = r; bi = i; }    // first-max = argmax
        }
        s_use  = (best >= 0.9f) ? 1 : 0;
        s_best = bi;
    }
    __syncthreads();

    const int gi = b * TPB + tid;                  // 43*256 == N_IN exactly
    if (!s_use) {
        if (gi < N_IN) {
            int sel = (g_maskbits[gi >> 5] >> (gi & 31)) & 1;
            g_xm[gi] = sel ? x[gi] : 0.0f;
        }
    } else {
        if (gi < N_IN) g_xm[gi] = 0.0f;
        grid_barrier();                            // xm zeroed (uniform path)
        if (gi < TOPK_K) {
            int idx = cached[s_best * TOPK_K + gi];
            atomicAdd(&g_xm[idx], x[idx]);         // duplicates = multiplicity
        }
    }
    grid_barrier();                                // xm final

    // ---- GEMV (exact R4 pattern: 1 row/warp, 4096 streams, 34.7us) ----
    const int row = b * 8 + wid;                   // 0..4095
    const float4* __restrict__ w4 = (const float4*)(W + (long long)row * N_IN);
    const float4* __restrict__ x4 = (const float4*)g_xm;

    float a0 = 0.0f, a1 = 0.0f;
    #pragma unroll 4
    for (int it = 0; it < 43; it++) {
        const int j = lane + it * 64;
        float4 w  = __ldcs(w4 + j);
        float4 v  = x4[j];
        a0 += w.x * v.x + w.y * v.y;
        a1 += w.z * v.z + w.w * v.w;
        float4 w2 = __ldcs(w4 + j + 32);
        float4 v2 = x4[j + 32];
        a0 += w2.x * v2.x + w2.y * v2.y;
        a1 += w2.z * v2.z + w2.w * v2.w;
    }
    float acc = a0 + a1;
    #pragma unroll
    for (int o = 16; o; o >>= 1) acc += __shfl_down_sync(0xffffffffu, acc, o);
    if (lane == 0) out[row] = acc + bias[row];
}

// ============================================================================
extern "C" void kernel_launch(void* const* d_in, const int* in_sizes, int n_in,
                              void* d_out, int out_size) {
    const float* x      = (const float*)d_in[0];
    const float* W      = (const float*)d_in[1];
    const float* bias   = (const float*)d_in[2];
    const int*   cached = (const int*)d_in[3];
    float*       out    = (float*)d_out;

    mega_kernel<<<GRID, TPB>>>(x, cached, W, bias, out);
}